// round 10
// baseline (speedup 1.0000x reference)
#include <cuda_runtime.h>

#define N_NODES 50000
#define N_EDGES 800000
#define IN_F    128
#define HEADS   4
#define OUT_F   32
#define HO      128            // HEADS*OUT_F
#define NEG_SLOPE 0.2f
#define EPS     1e-10f

#define SB      512                        // scan block size
#define NSCANB  ((N_NODES + SB - 1) / SB)  // 98

#define M_TILE  64
#define SXP     132                         // row stride for x-tile in smem
#define N_TILES ((N_NODES + M_TILE - 1) / M_TILE)   // 782

// ---------------- scratch (device globals) -----------------------------------
__device__ float g_h[N_NODES * HO];          // projected features [N, H*O]
__device__ float g_Wr[IN_F * HO];            // W re-laid out as [k][h*32+o]
__device__ float g_esrc[N_NODES * HEADS];
__device__ float g_edst[N_NODES * HEADS];
__device__ int   g_count[N_NODES];           // in-degree (preserved for k3)
__device__ int   g_cursor[N_NODES];
__device__ int   g_row[N_NODES + 1];         // block-local exclusive prefix
__device__ int   g_bsum[NSCANB];
__device__ int   g_boff[NSCANB];             // scanned block offsets
__device__ int   g_srcidx[N_EDGES];
__device__ float g_eval[N_EDGES * HEADS];    // exp(leakyrelu(logit)), CSR order

// ---------------- packed f32x2 helpers ---------------------------------------
__device__ __forceinline__ unsigned long long pack_dup(float a) {
    unsigned long long r;
    asm("mov.b64 %0, {%1, %1};" : "=l"(r) : "f"(a));
    return r;
}
__device__ __forceinline__ void ffma2(unsigned long long& acc,
                                      unsigned long long a,
                                      unsigned long long b) {
    asm("fma.rn.f32x2 %0, %1, %2, %0;" : "+l"(acc) : "l"(a), "l"(b));
}
__device__ __forceinline__ float2 unpack2(unsigned long long v) {
    float lo, hi;
    asm("mov.b64 {%0, %1}, %2;" : "=f"(lo), "=f"(hi) : "l"(v));
    return make_float2(lo, hi);
}

// ---------------- K0: zero histogram + cursors -------------------------------
__global__ void k0_zero() {
    int tid = blockIdx.x * blockDim.x + threadIdx.x;
    if (tid < N_NODES) { g_count[tid] = 0; g_cursor[tid] = 0; }
}

// ---------------- Kp: re-lay W -> g_Wr [k][n] --------------------------------
__global__ void k_prepW(const float* __restrict__ W) {
    int tid = blockIdx.x * blockDim.x + threadIdx.x;   // 16384
    if (tid >= IN_F * HO) return;
    int k = tid >> 7;
    int n = tid & 127;
    g_Wr[tid] = W[(n >> 5) * (IN_F * OUT_F) + k * OUT_F + (n & 31)];
}

// ---------------- K1: tiled GEMM (f32x2) + fused logit epilogue --------------
__global__ __launch_bounds__(256, 2)
void k1_gemm(const float* __restrict__ x,
             const float* __restrict__ a_src,
             const float* __restrict__ a_dst) {
    extern __shared__ float sm[];
    float* sW = sm;                        // 16384 floats [k][n]
    float* sx = sm + IN_F * HO;            // 64 * SXP floats [m][k]
    float* sA = sx + M_TILE * SXP;         // 128
    float* sD = sA + HO;                   // 128

    const int tid = threadIdx.x;
    const int tm  = tid >> 4;
    const int tn  = tid & 15;
    const int head = tn >> 2;

    {
        const float4* W4 = (const float4*)g_Wr;
        float4* sW4 = (float4*)sW;
        #pragma unroll
        for (int it = 0; it < 16; it++) sW4[it * 256 + tid] = W4[it * 256 + tid];
        if (tid < HO) { sA[tid] = a_src[tid]; sD[tid] = a_dst[tid]; }
    }

    const float4* x4 = (const float4*)x;
    float4* h4 = (float4*)g_h;

    for (int tile = blockIdx.x; tile < N_TILES; tile += gridDim.x) {
        const int mbase = tile * M_TILE;
        __syncthreads();
        #pragma unroll
        for (int it = 0; it < 8; it++) {
            int idx = it * 256 + tid;
            int m = idx >> 5;
            int q = idx & 31;
            int mg = mbase + m;
            float4 v = make_float4(0.f, 0.f, 0.f, 0.f);
            if (mg < N_NODES) v = x4[mg * 32 + q];
            *(float4*)(sx + m * SXP + q * 4) = v;
        }
        __syncthreads();

        unsigned long long acc[4][4];
        #pragma unroll
        for (int i = 0; i < 4; i++)
            #pragma unroll
            for (int j = 0; j < 4; j++) acc[i][j] = 0ULL;

        #pragma unroll 4
        for (int k = 0; k < IN_F; k += 2) {
            const ulonglong2* p0 = (const ulonglong2*)(sW + k * HO);
            const ulonglong2* p1 = (const ulonglong2*)(sW + (k + 1) * HO);
            ulonglong2 b00 = p0[tn * 2];
            ulonglong2 b01 = p0[tn * 2 + 1];
            ulonglong2 b10 = p1[tn * 2];
            ulonglong2 b11 = p1[tn * 2 + 1];
            #pragma unroll
            for (int mi = 0; mi < 4; mi++) {
                float2 a2 = *(const float2*)(sx + (tm * 4 + mi) * SXP + k);
                unsigned long long a0 = pack_dup(a2.x);
                unsigned long long a1 = pack_dup(a2.y);
                ffma2(acc[mi][0], a0, b00.x);
                ffma2(acc[mi][1], a0, b00.y);
                ffma2(acc[mi][2], a0, b01.x);
                ffma2(acc[mi][3], a0, b01.y);
                ffma2(acc[mi][0], a1, b10.x);
                ffma2(acc[mi][1], a1, b10.y);
                ffma2(acc[mi][2], a1, b11.x);
                ffma2(acc[mi][3], a1, b11.y);
            }
        }

        float as0 = sA[tn * 8 + 0], as1 = sA[tn * 8 + 1], as2 = sA[tn * 8 + 2], as3 = sA[tn * 8 + 3];
        float as4 = sA[tn * 8 + 4], as5 = sA[tn * 8 + 5], as6 = sA[tn * 8 + 6], as7 = sA[tn * 8 + 7];
        float ad0 = sD[tn * 8 + 0], ad1 = sD[tn * 8 + 1], ad2 = sD[tn * 8 + 2], ad3 = sD[tn * 8 + 3];
        float ad4 = sD[tn * 8 + 4], ad5 = sD[tn * 8 + 5], ad6 = sD[tn * 8 + 6], ad7 = sD[tn * 8 + 7];

        #pragma unroll
        for (int mi = 0; mi < 4; mi++) {
            int node = mbase + tm * 4 + mi;
            float2 p0 = unpack2(acc[mi][0]);
            float2 p1 = unpack2(acc[mi][1]);
            float2 p2 = unpack2(acc[mi][2]);
            float2 p3 = unpack2(acc[mi][3]);
            if (node < N_NODES) {
                h4[node * 32 + tn * 2]     = make_float4(p0.x, p0.y, p1.x, p1.y);
                h4[node * 32 + tn * 2 + 1] = make_float4(p2.x, p2.y, p3.x, p3.y);
            }
            float s = p0.x * as0 + p0.y * as1 + p1.x * as2 + p1.y * as3
                    + p2.x * as4 + p2.y * as5 + p3.x * as6 + p3.y * as7;
            float d = p0.x * ad0 + p0.y * ad1 + p1.x * ad2 + p1.y * ad3
                    + p2.x * ad4 + p2.y * ad5 + p3.x * ad6 + p3.y * ad7;
            s += __shfl_xor_sync(0xFFFFFFFFu, s, 1);
            d += __shfl_xor_sync(0xFFFFFFFFu, d, 1);
            s += __shfl_xor_sync(0xFFFFFFFFu, s, 2);
            d += __shfl_xor_sync(0xFFFFFFFFu, d, 2);
            if ((tn & 3) == 0 && node < N_NODES) {
                g_esrc[node * HEADS + head] = s;
                g_edst[node * HEADS + head] = d;
            }
        }
    }
}

// ---------------- K2a: in-degree histogram (2 edges/thread, int2) ------------
__global__ void k2_hist(const int* __restrict__ ei) {
    int t = blockIdx.x * blockDim.x + threadIdx.x;
    if (t >= N_EDGES / 2) return;
    int2 d = ((const int2*)(ei + N_EDGES))[t];
    atomicAdd(&g_count[d.x], 1);
    atomicAdd(&g_count[d.y], 1);
}

// ---------------- scan (2 kernels; block-offset add folded into consumers) ---
__global__ void k_scanA() {
    __shared__ int s[SB];
    int t = threadIdx.x;
    int g = blockIdx.x * SB + t;
    int v = (g < N_NODES) ? g_count[g] : 0;
    s[t] = v;
    __syncthreads();
    for (int off = 1; off < SB; off <<= 1) {
        int add = (t >= off) ? s[t - off] : 0;
        __syncthreads();
        s[t] += add;
        __syncthreads();
    }
    if (g < N_NODES) g_row[g] = s[t] - v;          // block-local exclusive
    if (t == SB - 1) g_bsum[blockIdx.x] = s[t];
}

__global__ void k_scanB() {
    __shared__ int s[128];
    int t = threadIdx.x;
    int v = (t < NSCANB) ? g_bsum[t] : 0;
    s[t] = v;
    __syncthreads();
    for (int off = 1; off < 128; off <<= 1) {
        int add = (t >= off) ? s[t - off] : 0;
        __syncthreads();
        s[t] += add;
        __syncthreads();
    }
    if (t < NSCANB) g_boff[t] = s[t] - v;          // exclusive block offsets
}

// ---------------- K2b: CSR scatter + exp(leakyrelu(logits)) ------------------
// Softmax shift-invariance: exp(e)/sum(exp(e)) == exp(e-m)/sum(exp(e-m)),
// so the reference's clamped seg-max cancels and we store exp(e) directly.
// Global row offset = g_row[dst] (block-local) + g_boff[dst>>9].
__global__ void k2_scatter(const int* __restrict__ ei) {
    int e = blockIdx.x * blockDim.x + threadIdx.x;
    if (e >= N_EDGES) return;
    int src = ei[e];
    int dst = ei[N_EDGES + e];
    int base = g_row[dst] + g_boff[dst >> 9];
    int pos = base + atomicAdd(&g_cursor[dst], 1);
    g_srcidx[pos] = src;
    float4 s = ((const float4*)g_esrc)[src];
    float4 d = ((const float4*)g_edst)[dst];
    float4 v;
    v.x = s.x + d.x; v.x = (v.x >= 0.f) ? v.x : NEG_SLOPE * v.x;
    v.y = s.y + d.y; v.y = (v.y >= 0.f) ? v.y : NEG_SLOPE * v.y;
    v.z = s.z + d.z; v.z = (v.z >= 0.f) ? v.z : NEG_SLOPE * v.z;
    v.w = s.w + d.w; v.w = (v.w >= 0.f) ? v.w : NEG_SLOPE * v.w;
    v.x = __expf(v.x);
    v.y = __expf(v.y);
    v.z = __expf(v.z);
    v.w = __expf(v.w);
    ((float4*)g_eval)[pos] = v;
}

// ---------------- K3: warp-per-node single-pass aggregation ------------------
__global__ void k3_agg(float* __restrict__ out) {
    int warp = (blockIdx.x * blockDim.x + threadIdx.x) >> 5;
    if (warp >= N_NODES) return;
    const int lane = threadIdx.x & 31;
    const int head = lane >> 3;
    const int quad = lane & 7;

    const int start = g_row[warp] + g_boff[warp >> 9];
    const int end   = start + g_count[warp];

    float4 acc = make_float4(0.f, 0.f, 0.f, 0.f);
    float ssum = 0.f;
    #pragma unroll 4
    for (int i = start; i < end; i++) {
        int src = g_srcidx[i];
        float ex = g_eval[i * HEADS + head];
        float4 hv = ((const float4*)g_h)[src * 32 + lane];
        acc.x += ex * hv.x;
        acc.y += ex * hv.y;
        acc.z += ex * hv.z;
        acc.w += ex * hv.w;
        if (quad == 0) ssum += ex;
    }
    ssum = __shfl_sync(0xFFFFFFFFu, ssum, head << 3);
    float inv = 1.f / (ssum + EPS);
    acc.x *= inv; acc.y *= inv; acc.z *= inv; acc.w *= inv;
    ((float4*)out)[warp * 32 + lane] = acc;
}

// ---------------- launch ------------------------------------------------------
extern "C" void kernel_launch(void* const* d_in, const int* in_sizes, int n_in,
                              void* d_out, int out_size) {
    const float* x     = (const float*)d_in[0];
    const int*   ei    = (const int*)d_in[1];
    const float* W     = (const float*)d_in[2];
    const float* a_src = (const float*)d_in[3];
    const float* a_dst = (const float*)d_in[4];
    float* out = (float*)d_out;

    k0_zero<<<(N_NODES + 255) / 256, 256>>>();
    k_prepW<<<(IN_F * HO + 255) / 256, 256>>>(W);

    {
        static bool attr_set = false;
        size_t smem = (IN_F * HO + M_TILE * SXP + 2 * HO) * sizeof(float); // 100352 B
        if (!attr_set) {
            cudaFuncSetAttribute(k1_gemm,
                                 cudaFuncAttributeMaxDynamicSharedMemorySize,
                                 (int)smem);
            attr_set = true;
        }
        k1_gemm<<<N_TILES, 256, smem>>>(x, a_src, a_dst);
    }

    k2_hist<<<(N_EDGES / 2 + 255) / 256, 256>>>(ei);
    k_scanA<<<NSCANB, SB>>>();
    k_scanB<<<1, 128>>>();
    k2_scatter<<<(N_EDGES + 255) / 256, 256>>>(ei);

    k3_agg<<<(N_NODES * 32 + 255) / 256, 256>>>(out);
}

// round 16
// speedup vs baseline: 1.0637x; 1.0637x over previous
#include <cuda_runtime.h>
#include <cuda_fp16.h>

#define N_NODES 50000
#define N_EDGES 800000
#define IN_F    128
#define HEADS   4
#define OUT_F   32
#define HO      128            // HEADS*OUT_F
#define NEG_SLOPE 0.2f
#define EPS     1e-10f

#define SB      512                        // scan block size
#define NSCANB  ((N_NODES + SB - 1) / SB)  // 98

#define M_TILE  64
#define SXP     132                         // row stride for x-tile in smem
#define N_TILES ((N_NODES + M_TILE - 1) / M_TILE)   // 782

// ---------------- scratch (device globals) -----------------------------------
__device__ unsigned int g_hh[N_NODES * 64];  // h packed as half2 [N][64]
__device__ float g_Wr[IN_F * HO];            // W re-laid out as [k][h*32+o]
__device__ float g_esrc[N_NODES * HEADS];
__device__ float g_edst[N_NODES * HEADS];
__device__ int   g_count[N_NODES];           // in-degree (preserved for k3)
__device__ int   g_cursor[N_NODES];
__device__ int   g_row[N_NODES + 1];         // block-local exclusive prefix
__device__ int   g_bsum[NSCANB];
__device__ int   g_boff[NSCANB];             // scanned block offsets
__device__ int   g_srcidx[N_EDGES];
__device__ float g_eval[N_EDGES * HEADS];    // exp(leakyrelu(logit)), CSR order

// ---------------- packed f32x2 helpers ---------------------------------------
__device__ __forceinline__ unsigned long long pack_dup(float a) {
    unsigned long long r;
    asm("mov.b64 %0, {%1, %1};" : "=l"(r) : "f"(a));
    return r;
}
__device__ __forceinline__ void ffma2(unsigned long long& acc,
                                      unsigned long long a,
                                      unsigned long long b) {
    asm("fma.rn.f32x2 %0, %1, %2, %0;" : "+l"(acc) : "l"(a), "l"(b));
}
__device__ __forceinline__ float2 unpack2(unsigned long long v) {
    float lo, hi;
    asm("mov.b64 {%0, %1}, %2;" : "=f"(lo), "=f"(hi) : "l"(v));
    return make_float2(lo, hi);
}
__device__ __forceinline__ unsigned int h2pack(float2 f) {
    __half2 h = __float22half2_rn(f);
    return *(unsigned int*)&h;
}

// ---------------- K0: zero histogram + cursors -------------------------------
__global__ void k0_zero() {
    int tid = blockIdx.x * blockDim.x + threadIdx.x;
    if (tid < N_NODES) { g_count[tid] = 0; g_cursor[tid] = 0; }
}

// ---------------- Kp: re-lay W -> g_Wr [k][n] --------------------------------
__global__ void k_prepW(const float* __restrict__ W) {
    int tid = blockIdx.x * blockDim.x + threadIdx.x;   // 16384
    if (tid >= IN_F * HO) return;
    int k = tid >> 7;
    int n = tid & 127;
    g_Wr[tid] = W[(n >> 5) * (IN_F * OUT_F) + k * OUT_F + (n & 31)];
}

// ---------------- K1: tiled GEMM (f32x2) + fused logit epilogue --------------
__global__ __launch_bounds__(256, 2)
void k1_gemm(const float* __restrict__ x,
             const float* __restrict__ a_src,
             const float* __restrict__ a_dst) {
    extern __shared__ float sm[];
    float* sW = sm;                        // 16384 floats [k][n]
    float* sx = sm + IN_F * HO;            // 64 * SXP floats [m][k]
    float* sA = sx + M_TILE * SXP;         // 128
    float* sD = sA + HO;                   // 128

    const int tid = threadIdx.x;
    const int tm  = tid >> 4;
    const int tn  = tid & 15;
    const int head = tn >> 2;

    {
        const float4* W4 = (const float4*)g_Wr;
        float4* sW4 = (float4*)sW;
        #pragma unroll
        for (int it = 0; it < 16; it++) sW4[it * 256 + tid] = W4[it * 256 + tid];
        if (tid < HO) { sA[tid] = a_src[tid]; sD[tid] = a_dst[tid]; }
    }

    const float4* x4 = (const float4*)x;

    for (int tile = blockIdx.x; tile < N_TILES; tile += gridDim.x) {
        const int mbase = tile * M_TILE;
        __syncthreads();
        #pragma unroll
        for (int it = 0; it < 8; it++) {
            int idx = it * 256 + tid;
            int m = idx >> 5;
            int q = idx & 31;
            int mg = mbase + m;
            float4 v = make_float4(0.f, 0.f, 0.f, 0.f);
            if (mg < N_NODES) v = x4[mg * 32 + q];
            *(float4*)(sx + m * SXP + q * 4) = v;
        }
        __syncthreads();

        unsigned long long acc[4][4];
        #pragma unroll
        for (int i = 0; i < 4; i++)
            #pragma unroll
            for (int j = 0; j < 4; j++) acc[i][j] = 0ULL;

        #pragma unroll 4
        for (int k = 0; k < IN_F; k += 2) {
            const ulonglong2* p0 = (const ulonglong2*)(sW + k * HO);
            const ulonglong2* p1 = (const ulonglong2*)(sW + (k + 1) * HO);
            ulonglong2 b00 = p0[tn * 2];
            ulonglong2 b01 = p0[tn * 2 + 1];
            ulonglong2 b10 = p1[tn * 2];
            ulonglong2 b11 = p1[tn * 2 + 1];
            #pragma unroll
            for (int mi = 0; mi < 4; mi++) {
                float2 a2 = *(const float2*)(sx + (tm * 4 + mi) * SXP + k);
                unsigned long long a0 = pack_dup(a2.x);
                unsigned long long a1 = pack_dup(a2.y);
                ffma2(acc[mi][0], a0, b00.x);
                ffma2(acc[mi][1], a0, b00.y);
                ffma2(acc[mi][2], a0, b01.x);
                ffma2(acc[mi][3], a0, b01.y);
                ffma2(acc[mi][0], a1, b10.x);
                ffma2(acc[mi][1], a1, b10.y);
                ffma2(acc[mi][2], a1, b11.x);
                ffma2(acc[mi][3], a1, b11.y);
            }
        }

        float as0 = sA[tn * 8 + 0], as1 = sA[tn * 8 + 1], as2 = sA[tn * 8 + 2], as3 = sA[tn * 8 + 3];
        float as4 = sA[tn * 8 + 4], as5 = sA[tn * 8 + 5], as6 = sA[tn * 8 + 6], as7 = sA[tn * 8 + 7];
        float ad0 = sD[tn * 8 + 0], ad1 = sD[tn * 8 + 1], ad2 = sD[tn * 8 + 2], ad3 = sD[tn * 8 + 3];
        float ad4 = sD[tn * 8 + 4], ad5 = sD[tn * 8 + 5], ad6 = sD[tn * 8 + 6], ad7 = sD[tn * 8 + 7];

        #pragma unroll
        for (int mi = 0; mi < 4; mi++) {
            int node = mbase + tm * 4 + mi;
            float2 p0 = unpack2(acc[mi][0]);
            float2 p1 = unpack2(acc[mi][1]);
            float2 p2 = unpack2(acc[mi][2]);
            float2 p3 = unpack2(acc[mi][3]);
            if (node < N_NODES) {
                uint4 hp;
                hp.x = h2pack(p0);
                hp.y = h2pack(p1);
                hp.z = h2pack(p2);
                hp.w = h2pack(p3);
                ((uint4*)g_hh)[node * 16 + tn] = hp;   // halves tn*8..tn*8+7
            }
            float s = p0.x * as0 + p0.y * as1 + p1.x * as2 + p1.y * as3
                    + p2.x * as4 + p2.y * as5 + p3.x * as6 + p3.y * as7;
            float d = p0.x * ad0 + p0.y * ad1 + p1.x * ad2 + p1.y * ad3
                    + p2.x * ad4 + p2.y * ad5 + p3.x * ad6 + p3.y * ad7;
            s += __shfl_xor_sync(0xFFFFFFFFu, s, 1);
            d += __shfl_xor_sync(0xFFFFFFFFu, d, 1);
            s += __shfl_xor_sync(0xFFFFFFFFu, s, 2);
            d += __shfl_xor_sync(0xFFFFFFFFu, d, 2);
            if ((tn & 3) == 0 && node < N_NODES) {
                g_esrc[node * HEADS + head] = s;
                g_edst[node * HEADS + head] = d;
            }
        }
    }
}

// ---------------- K2a: in-degree histogram (2 edges/thread, int2) ------------
__global__ void k2_hist(const int* __restrict__ ei) {
    int t = blockIdx.x * blockDim.x + threadIdx.x;
    if (t >= N_EDGES / 2) return;
    int2 d = ((const int2*)(ei + N_EDGES))[t];
    atomicAdd(&g_count[d.x], 1);
    atomicAdd(&g_count[d.y], 1);
}

// ---------------- scan (2 kernels; block-offset add folded into consumers) ---
__global__ void k_scanA() {
    __shared__ int s[SB];
    int t = threadIdx.x;
    int g = blockIdx.x * SB + t;
    int v = (g < N_NODES) ? g_count[g] : 0;
    s[t] = v;
    __syncthreads();
    for (int off = 1; off < SB; off <<= 1) {
        int add = (t >= off) ? s[t - off] : 0;
        __syncthreads();
        s[t] += add;
        __syncthreads();
    }
    if (g < N_NODES) g_row[g] = s[t] - v;          // block-local exclusive
    if (t == SB - 1) g_bsum[blockIdx.x] = s[t];
}

__global__ void k_scanB() {
    __shared__ int s[128];
    int t = threadIdx.x;
    int v = (t < NSCANB) ? g_bsum[t] : 0;
    s[t] = v;
    __syncthreads();
    for (int off = 1; off < 128; off <<= 1) {
        int add = (t >= off) ? s[t - off] : 0;
        __syncthreads();
        s[t] += add;
        __syncthreads();
    }
    if (t < NSCANB) g_boff[t] = s[t] - v;          // exclusive block offsets
}

// ---------------- K2b: CSR scatter + exp(leakyrelu(logits)) ------------------
// Softmax shift-invariance: exp(e)/sum(exp(e)) == exp(e-m)/sum(exp(e-m)),
// so the reference's clamped seg-max cancels and we store exp(e) directly.
__global__ void k2_scatter(const int* __restrict__ ei) {
    int e = blockIdx.x * blockDim.x + threadIdx.x;
    if (e >= N_EDGES) return;
    int src = ei[e];
    int dst = ei[N_EDGES + e];
    int base = g_row[dst] + g_boff[dst >> 9];
    int pos = base + atomicAdd(&g_cursor[dst], 1);
    g_srcidx[pos] = src;
    float4 s = ((const float4*)g_esrc)[src];
    float4 d = ((const float4*)g_edst)[dst];
    float4 v;
    v.x = s.x + d.x; v.x = (v.x >= 0.f) ? v.x : NEG_SLOPE * v.x;
    v.y = s.y + d.y; v.y = (v.y >= 0.f) ? v.y : NEG_SLOPE * v.y;
    v.z = s.z + d.z; v.z = (v.z >= 0.f) ? v.z : NEG_SLOPE * v.z;
    v.w = s.w + d.w; v.w = (v.w >= 0.f) ? v.w : NEG_SLOPE * v.w;
    v.x = __expf(v.x);
    v.y = __expf(v.y);
    v.z = __expf(v.z);
    v.w = __expf(v.w);
    ((float4*)g_eval)[pos] = v;
}

// ---------------- K3: warp-per-node single-pass aggregation (fp16 gather) ----
__global__ void k3_agg(float* __restrict__ out) {
    int warp = (blockIdx.x * blockDim.x + threadIdx.x) >> 5;
    if (warp >= N_NODES) return;
    const int lane = threadIdx.x & 31;
    const int head = lane >> 3;
    const int quad = lane & 7;

    const int start = g_row[warp] + g_boff[warp >> 9];
    const int end   = start + g_count[warp];

    float4 acc = make_float4(0.f, 0.f, 0.f, 0.f);
    float ssum = 0.f;
    #pragma unroll 4
    for (int i = start; i < end; i++) {
        int src = g_srcidx[i];
        float ex = g_eval[i * HEADS + head];
        uint2 hp = ((const uint2*)g_hh)[src * 32 + lane];   // halves lane*4..+3
        float2 f0 = __half22float2(*(const __half2*)&hp.x);
        float2 f1 = __half22float2(*(const __half2*)&hp.y);
        acc.x += ex * f0.x;
        acc.y += ex * f0.y;
        acc.z += ex * f1.x;
        acc.w += ex * f1.y;
        if (quad == 0) ssum += ex;
    }
    ssum = __shfl_sync(0xFFFFFFFFu, ssum, head << 3);
    float inv = 1.f / (ssum + EPS);
    acc.x *= inv; acc.y *= inv; acc.z *= inv; acc.w *= inv;
    ((float4*)out)[warp * 32 + lane] = acc;
}

// ---------------- launch ------------------------------------------------------
extern "C" void kernel_launch(void* const* d_in, const int* in_sizes, int n_in,
                              void* d_out, int out_size) {
    const float* x     = (const float*)d_in[0];
    const int*   ei    = (const int*)d_in[1];
    const float* W     = (const float*)d_in[2];
    const float* a_src = (const float*)d_in[3];
    const float* a_dst = (const float*)d_in[4];
    float* out = (float*)d_out;

    k0_zero<<<(N_NODES + 255) / 256, 256>>>();
    k_prepW<<<(IN_F * HO + 255) / 256, 256>>>(W);

    {
        static bool attr_set = false;
        size_t smem = (IN_F * HO + M_TILE * SXP + 2 * HO) * sizeof(float); // 100352 B
        if (!attr_set) {
            cudaFuncSetAttribute(k1_gemm,
                                 cudaFuncAttributeMaxDynamicSharedMemorySize,
                                 (int)smem);
            attr_set = true;
        }
        k1_gemm<<<N_TILES, 256, smem>>>(x, a_src, a_dst);
    }

    k2_hist<<<(N_EDGES / 2 + 255) / 256, 256>>>(ei);
    k_scanA<<<NSCANB, SB>>>();
    k_scanB<<<1, 128>>>();
    k2_scatter<<<(N_EDGES + 255) / 256, 256>>>(ei);

    k3_agg<<<(N_NODES * 32 + 255) / 256, 256>>>(out);
}

// round 17
// speedup vs baseline: 1.0817x; 1.0168x over previous
#include <cuda_runtime.h>
#include <cuda_fp16.h>

#define N_NODES 50000
#define N_EDGES 800000
#define IN_F    128
#define HEADS   4
#define OUT_F   32
#define HO      128            // HEADS*OUT_F
#define NEG_SLOPE 0.2f
#define EPS     1e-10f

#define SB      512                        // scan block size
#define NSCANB  ((N_NODES + SB - 1) / SB)  // 98

#define M_TILE  64
#define SXP     132                         // row stride for x-tile in smem
#define N_TILES ((N_NODES + M_TILE - 1) / M_TILE)   // 782

// ---------------- scratch (device globals) -----------------------------------
__device__ unsigned int g_hh[N_NODES * 64];  // h packed as half2 [N][64]
__device__ float g_Wr[IN_F * HO];            // W re-laid out as [k][h*32+o]
__device__ float g_esrc[N_NODES * HEADS];
__device__ float g_edst[N_NODES * HEADS];
__device__ int   g_count[N_NODES];           // in-degree (preserved for k3)
__device__ int   g_cursor[N_NODES];
__device__ int   g_row[N_NODES + 1];         // block-local exclusive prefix
__device__ int   g_bsum[NSCANB];
__device__ int   g_boff[NSCANB];             // scanned block offsets
__device__ int   g_srcidx[N_EDGES];
__device__ float g_eval[N_EDGES * HEADS];    // exp(leakyrelu(logit)), CSR order

// ---------------- packed f32x2 helpers ---------------------------------------
__device__ __forceinline__ unsigned long long pack_dup(float a) {
    unsigned long long r;
    asm("mov.b64 %0, {%1, %1};" : "=l"(r) : "f"(a));
    return r;
}
__device__ __forceinline__ void ffma2(unsigned long long& acc,
                                      unsigned long long a,
                                      unsigned long long b) {
    asm("fma.rn.f32x2 %0, %1, %2, %0;" : "+l"(acc) : "l"(a), "l"(b));
}
__device__ __forceinline__ float2 unpack2(unsigned long long v) {
    float lo, hi;
    asm("mov.b64 {%0, %1}, %2;" : "=f"(lo), "=f"(hi) : "l"(v));
    return make_float2(lo, hi);
}
__device__ __forceinline__ unsigned int h2pack(float2 f) {
    __half2 h = __float22half2_rn(f);
    return *(unsigned int*)&h;
}

// ---------------- K0: zero histogram + cursors -------------------------------
__global__ void k0_zero() {
    int tid = blockIdx.x * blockDim.x + threadIdx.x;
    if (tid < N_NODES) { g_count[tid] = 0; g_cursor[tid] = 0; }
}

// ---------------- Kp: re-lay W -> g_Wr [k][n] --------------------------------
__global__ void k_prepW(const float* __restrict__ W) {
    int tid = blockIdx.x * blockDim.x + threadIdx.x;   // 16384
    if (tid >= IN_F * HO) return;
    int k = tid >> 7;
    int n = tid & 127;
    g_Wr[tid] = W[(n >> 5) * (IN_F * OUT_F) + k * OUT_F + (n & 31)];
}

// ---------------- K1: tiled GEMM (f32x2) + fused logit epilogue --------------
__global__ __launch_bounds__(256, 2)
void k1_gemm(const float* __restrict__ x,
             const float* __restrict__ a_src,
             const float* __restrict__ a_dst) {
    extern __shared__ float sm[];
    float* sW = sm;                        // 16384 floats [k][n]
    float* sx = sm + IN_F * HO;            // 64 * SXP floats [m][k]
    float* sA = sx + M_TILE * SXP;         // 128
    float* sD = sA + HO;                   // 128

    const int tid = threadIdx.x;
    const int tm  = tid >> 4;
    const int tn  = tid & 15;
    const int head = tn >> 2;

    {
        const float4* W4 = (const float4*)g_Wr;
        float4* sW4 = (float4*)sW;
        #pragma unroll
        for (int it = 0; it < 16; it++) sW4[it * 256 + tid] = W4[it * 256 + tid];
        if (tid < HO) { sA[tid] = a_src[tid]; sD[tid] = a_dst[tid]; }
    }

    const float4* x4 = (const float4*)x;

    for (int tile = blockIdx.x; tile < N_TILES; tile += gridDim.x) {
        const int mbase = tile * M_TILE;
        __syncthreads();
        #pragma unroll
        for (int it = 0; it < 8; it++) {
            int idx = it * 256 + tid;
            int m = idx >> 5;
            int q = idx & 31;
            int mg = mbase + m;
            float4 v = make_float4(0.f, 0.f, 0.f, 0.f);
            if (mg < N_NODES) v = x4[mg * 32 + q];
            *(float4*)(sx + m * SXP + q * 4) = v;
        }
        __syncthreads();

        unsigned long long acc[4][4];
        #pragma unroll
        for (int i = 0; i < 4; i++)
            #pragma unroll
            for (int j = 0; j < 4; j++) acc[i][j] = 0ULL;

        #pragma unroll 4
        for (int k = 0; k < IN_F; k += 2) {
            const ulonglong2* p0 = (const ulonglong2*)(sW + k * HO);
            const ulonglong2* p1 = (const ulonglong2*)(sW + (k + 1) * HO);
            ulonglong2 b00 = p0[tn * 2];
            ulonglong2 b01 = p0[tn * 2 + 1];
            ulonglong2 b10 = p1[tn * 2];
            ulonglong2 b11 = p1[tn * 2 + 1];
            #pragma unroll
            for (int mi = 0; mi < 4; mi++) {
                float2 a2 = *(const float2*)(sx + (tm * 4 + mi) * SXP + k);
                unsigned long long a0 = pack_dup(a2.x);
                unsigned long long a1 = pack_dup(a2.y);
                ffma2(acc[mi][0], a0, b00.x);
                ffma2(acc[mi][1], a0, b00.y);
                ffma2(acc[mi][2], a0, b01.x);
                ffma2(acc[mi][3], a0, b01.y);
                ffma2(acc[mi][0], a1, b10.x);
                ffma2(acc[mi][1], a1, b10.y);
                ffma2(acc[mi][2], a1, b11.x);
                ffma2(acc[mi][3], a1, b11.y);
            }
        }

        float as0 = sA[tn * 8 + 0], as1 = sA[tn * 8 + 1], as2 = sA[tn * 8 + 2], as3 = sA[tn * 8 + 3];
        float as4 = sA[tn * 8 + 4], as5 = sA[tn * 8 + 5], as6 = sA[tn * 8 + 6], as7 = sA[tn * 8 + 7];
        float ad0 = sD[tn * 8 + 0], ad1 = sD[tn * 8 + 1], ad2 = sD[tn * 8 + 2], ad3 = sD[tn * 8 + 3];
        float ad4 = sD[tn * 8 + 4], ad5 = sD[tn * 8 + 5], ad6 = sD[tn * 8 + 6], ad7 = sD[tn * 8 + 7];

        #pragma unroll
        for (int mi = 0; mi < 4; mi++) {
            int node = mbase + tm * 4 + mi;
            float2 p0 = unpack2(acc[mi][0]);
            float2 p1 = unpack2(acc[mi][1]);
            float2 p2 = unpack2(acc[mi][2]);
            float2 p3 = unpack2(acc[mi][3]);
            if (node < N_NODES) {
                uint4 hp;
                hp.x = h2pack(p0);
                hp.y = h2pack(p1);
                hp.z = h2pack(p2);
                hp.w = h2pack(p3);
                ((uint4*)g_hh)[node * 16 + tn] = hp;   // halves tn*8..tn*8+7
            }
            float s = p0.x * as0 + p0.y * as1 + p1.x * as2 + p1.y * as3
                    + p2.x * as4 + p2.y * as5 + p3.x * as6 + p3.y * as7;
            float d = p0.x * ad0 + p0.y * ad1 + p1.x * ad2 + p1.y * ad3
                    + p2.x * ad4 + p2.y * ad5 + p3.x * ad6 + p3.y * ad7;
            s += __shfl_xor_sync(0xFFFFFFFFu, s, 1);
            d += __shfl_xor_sync(0xFFFFFFFFu, d, 1);
            s += __shfl_xor_sync(0xFFFFFFFFu, s, 2);
            d += __shfl_xor_sync(0xFFFFFFFFu, d, 2);
            if ((tn & 3) == 0 && node < N_NODES) {
                g_esrc[node * HEADS + head] = s;
                g_edst[node * HEADS + head] = d;
            }
        }
    }
}

// ---------------- K2a: in-degree histogram (2 edges/thread, int2) ------------
__global__ void k2_hist(const int* __restrict__ ei) {
    int t = blockIdx.x * blockDim.x + threadIdx.x;
    if (t >= N_EDGES / 2) return;
    int2 d = ((const int2*)(ei + N_EDGES))[t];
    atomicAdd(&g_count[d.x], 1);
    atomicAdd(&g_count[d.y], 1);
}

// ---------------- scan (2 kernels; block-offset add folded into consumers) ---
__global__ void k_scanA() {
    __shared__ int s[SB];
    int t = threadIdx.x;
    int g = blockIdx.x * SB + t;
    int v = (g < N_NODES) ? g_count[g] : 0;
    s[t] = v;
    __syncthreads();
    for (int off = 1; off < SB; off <<= 1) {
        int add = (t >= off) ? s[t - off] : 0;
        __syncthreads();
        s[t] += add;
        __syncthreads();
    }
    if (g < N_NODES) g_row[g] = s[t] - v;          // block-local exclusive
    if (t == SB - 1) g_bsum[blockIdx.x] = s[t];
}

__global__ void k_scanB() {
    __shared__ int s[128];
    int t = threadIdx.x;
    int v = (t < NSCANB) ? g_bsum[t] : 0;
    s[t] = v;
    __syncthreads();
    for (int off = 1; off < 128; off <<= 1) {
        int add = (t >= off) ? s[t - off] : 0;
        __syncthreads();
        s[t] += add;
        __syncthreads();
    }
    if (t < NSCANB) g_boff[t] = s[t] - v;          // exclusive block offsets
}

// ---------------- K2b: CSR scatter + exp(leakyrelu(logits)) ------------------
// Softmax shift-invariance: exp(e)/sum(exp(e)) == exp(e-m)/sum(exp(e-m)),
// so the reference's clamped seg-max cancels and we store exp(e) directly.
__global__ void k2_scatter(const int* __restrict__ ei) {
    int e = blockIdx.x * blockDim.x + threadIdx.x;
    if (e >= N_EDGES) return;
    int src = ei[e];
    int dst = ei[N_EDGES + e];
    int base = g_row[dst] + g_boff[dst >> 9];
    int pos = base + atomicAdd(&g_cursor[dst], 1);
    g_srcidx[pos] = src;
    float4 s = ((const float4*)g_esrc)[src];
    float4 d = ((const float4*)g_edst)[dst];
    float4 v;
    v.x = s.x + d.x; v.x = (v.x >= 0.f) ? v.x : NEG_SLOPE * v.x;
    v.y = s.y + d.y; v.y = (v.y >= 0.f) ? v.y : NEG_SLOPE * v.y;
    v.z = s.z + d.z; v.z = (v.z >= 0.f) ? v.z : NEG_SLOPE * v.z;
    v.w = s.w + d.w; v.w = (v.w >= 0.f) ? v.w : NEG_SLOPE * v.w;
    v.x = __expf(v.x);
    v.y = __expf(v.y);
    v.z = __expf(v.z);
    v.w = __expf(v.w);
    ((float4*)g_eval)[pos] = v;
}

// ---------------- K3: warp-per-node, 2 edges/iter (fp16 uint4 gather) --------
// Half-warp per edge: lanes 0-15 -> edge i, lanes 16-31 -> edge i+1.
// Lane covers output cols (lane&15)*8 .. +7  (head = (lane&15)>>2).
// Edge-set partials merged via shfl_xor(16) at the end.
__global__ void k3_agg(float* __restrict__ out) {
    int warp = (blockIdx.x * blockDim.x + threadIdx.x) >> 5;
    if (warp >= N_NODES) return;
    const int lane = threadIdx.x & 31;
    const int hl   = lane & 15;        // lane within half-warp
    const int sub  = lane >> 4;        // which edge of the pair
    const int head = hl >> 2;

    const int start = g_row[warp] + g_boff[warp >> 9];
    const int end   = start + g_count[warp];

    float a0 = 0.f, a1 = 0.f, a2 = 0.f, a3 = 0.f;
    float a4 = 0.f, a5 = 0.f, a6 = 0.f, a7 = 0.f;
    float ssum = 0.f;

    const uint4* hh4 = (const uint4*)g_hh;

    #pragma unroll 2
    for (int i = start; i < end; i += 2) {
        int e = i + sub;
        float ex = 0.f;
        int src = 0;
        if (e < end) {
            src = g_srcidx[e];
            ex  = g_eval[e * HEADS + head];
        }
        uint4 hp = hh4[src * 16 + hl];          // 16 B: halves hl*8..hl*8+7
        float2 f0 = __half22float2(*(const __half2*)&hp.x);
        float2 f1 = __half22float2(*(const __half2*)&hp.y);
        float2 f2 = __half22float2(*(const __half2*)&hp.z);
        float2 f3 = __half22float2(*(const __half2*)&hp.w);
        a0 += ex * f0.x; a1 += ex * f0.y;
        a2 += ex * f1.x; a3 += ex * f1.y;
        a4 += ex * f2.x; a5 += ex * f2.y;
        a6 += ex * f3.x; a7 += ex * f3.y;
        if ((hl & 3) == 0) ssum += ex;
    }

    // merge the two half-warps (same cols, disjoint edge sets)
    a0 += __shfl_xor_sync(0xFFFFFFFFu, a0, 16);
    a1 += __shfl_xor_sync(0xFFFFFFFFu, a1, 16);
    a2 += __shfl_xor_sync(0xFFFFFFFFu, a2, 16);
    a3 += __shfl_xor_sync(0xFFFFFFFFu, a3, 16);
    a4 += __shfl_xor_sync(0xFFFFFFFFu, a4, 16);
    a5 += __shfl_xor_sync(0xFFFFFFFFu, a5, 16);
    a6 += __shfl_xor_sync(0xFFFFFFFFu, a6, 16);
    a7 += __shfl_xor_sync(0xFFFFFFFFu, a7, 16);
    ssum += __shfl_xor_sync(0xFFFFFFFFu, ssum, 16);
    // head h's sum lives at lane 4h; broadcast to all lanes of that head
    ssum = __shfl_sync(0xFFFFFFFFu, ssum, lane & 12);

    float inv = 1.f / (ssum + EPS);
    // lane writes float4 #(hl*2 + sub): sub 0 -> cols hl*8..+3, sub 1 -> +4..+7
    float4 o;
    if (sub == 0) o = make_float4(a0 * inv, a1 * inv, a2 * inv, a3 * inv);
    else          o = make_float4(a4 * inv, a5 * inv, a6 * inv, a7 * inv);
    ((float4*)out)[warp * 32 + hl * 2 + sub] = o;
}

// ---------------- launch ------------------------------------------------------
extern "C" void kernel_launch(void* const* d_in, const int* in_sizes, int n_in,
                              void* d_out, int out_size) {
    const float* x     = (const float*)d_in[0];
    const int*   ei    = (const int*)d_in[1];
    const float* W     = (const float*)d_in[2];
    const float* a_src = (const float*)d_in[3];
    const float* a_dst = (const float*)d_in[4];
    float* out = (float*)d_out;

    k0_zero<<<(N_NODES + 255) / 256, 256>>>();
    k_prepW<<<(IN_F * HO + 255) / 256, 256>>>(W);

    {
        static bool attr_set = false;
        size_t smem = (IN_F * HO + M_TILE * SXP + 2 * HO) * sizeof(float); // 100352 B
        if (!attr_set) {
            cudaFuncSetAttribute(k1_gemm,
                                 cudaFuncAttributeMaxDynamicSharedMemorySize,
                                 (int)smem);
            attr_set = true;
        }
        k1_gemm<<<N_TILES, 256, smem>>>(x, a_src, a_dst);
    }

    k2_hist<<<(N_EDGES / 2 + 255) / 256, 256>>>(ei);
    k_scanA<<<NSCANB, SB>>>();
    k_scanB<<<1, 128>>>();
    k2_scatter<<<(N_EDGES + 255) / 256, 256>>>(ei);

    k3_agg<<<(N_NODES * 32 + 255) / 256, 256>>>(out);
}